// round 1
// baseline (speedup 1.0000x reference)
#include <cuda_runtime.h>
#include <math.h>

// Problem constants
#define S_DIM 500
#define T_DIM 8
#define B_DIM 8
#define FO    64
#define FI    32
#define CN    4096      // B*T*FO columns
#define NROWS 32000     // S*B*T rows when viewed as [rows, 64]

// Scratch (device globals; allocation-free per harness rules)
__device__ float g_Z [S_DIM * CN];
__device__ float g_M1[S_DIM * CN];
__device__ float g_M2[S_DIM * CN];
__device__ float g_Y1[S_DIM * CN];
__device__ float g_Y2[S_DIM * CN];

// Packed fp32x2 helpers (sm_103a; ptxas won't auto-fuse -> inline PTX)
#define DUP2(d, a)       asm("mov.b64 %0, {%1, %1};" : "=l"(d) : "f"(a))
#define FMA2(d, a, b, c) asm("fma.rn.f32x2 %0, %1, %2, %3;" : "=l"(d) : "l"(a), "l"(b), "l"(c))

static __device__ __forceinline__ float2 unpack2(unsigned long long v) {
    float2 r;
    asm("mov.b64 {%0, %1}, %2;" : "=f"(r.x), "=f"(r.y) : "l"(v));
    return r;
}

// ---------------------------------------------------------------------------
// K0: input projection + pack:  Z[s, (b,t,f)] = sum_i x[b,t,s,i] * W1[f,i] + b1[f]
// grid: (64 slabs bt, 10 chunks of 50 s), 256 threads
// ---------------------------------------------------------------------------
__global__ __launch_bounds__(256)
void k_inproj(const float* __restrict__ x, const float* __restrict__ W1,
              const float* __restrict__ b1)
{
    __shared__ float ws[FO][FI + 1];
    __shared__ float xs[50][FI];
    __shared__ float bs[FO];

    const int tid = threadIdx.x;
    const int bt  = blockIdx.x;        // 0..63  (b*8+t)
    const int s0  = blockIdx.y * 50;

    for (int idx = tid; idx < FO * FI; idx += 256)
        ws[idx >> 5][idx & 31] = W1[idx];
    if (tid < FO) bs[tid] = b1[tid];
    const float* xp = x + (bt * S_DIM + s0) * FI;
    for (int idx = tid; idx < 50 * FI; idx += 256)
        xs[idx >> 5][idx & 31] = xp[idx];
    __syncthreads();

    const int f   = tid & 63;
    const int sl0 = tid >> 6;
    for (int sl = sl0; sl < 50; sl += 4) {
        float acc = bs[f];
        #pragma unroll
        for (int i = 0; i < FI; i++)
            acc += xs[sl][i] * ws[f][i];
        g_Z[(s0 + sl) * CN + bt * FO + f] = acc;
    }
}

// ---------------------------------------------------------------------------
// Main GEMM: C[500,4096] = A[500,500] @ X[500,4096]   (fp32, f32x2 packed)
// BM=64, BN=128, BK=16, 256 threads, thread tile 4x8 (as 4x4 f32x2 pairs)
// grid: (32 n-tiles, 8 m-tiles)
// ---------------------------------------------------------------------------
__global__ __launch_bounds__(256)
void k_gemm(const float* __restrict__ A, const float* __restrict__ X,
            float* __restrict__ C)
{
    __shared__ __align__(16) float sA[2][16][68];
    __shared__ __align__(16) float sB[2][16][128];

    const int tid = threadIdx.x;
    const int n0  = blockIdx.x * 128;
    const int m0  = blockIdx.y * 64;

    const int tn2 = (tid & 15) * 2;   // col pair base within 32-col group
    const int tm4 = (tid >> 4) * 4;   // row base

    const int aRow = tid >> 2;            // 0..63
    const int aK   = (tid & 3) * 4;       // 0,4,8,12
    const int bK   = tid >> 4;            // 0..15
    const int bCol = (tid & 15) * 8;      // 0..120

    unsigned long long acc[4][4];
    #pragma unroll
    for (int i = 0; i < 4; i++)
        #pragma unroll
        for (int j = 0; j < 4; j++) acc[i][j] = 0ULL;

    const int KT = 32;  // ceil(500/16)

    float4 aReg = make_float4(0.f, 0.f, 0.f, 0.f);
    float4 bReg0 = aReg, bReg1 = aReg;

    // prologue: k-tile 0
    if (m0 + aRow < S_DIM)
        aReg = *(const float4*)(A + (m0 + aRow) * S_DIM + aK);
    {
        const float* bp = X + bK * CN + n0 + bCol;
        bReg0 = *(const float4*)(bp);
        bReg1 = *(const float4*)(bp + 4);
    }
    int buf = 0;
    sA[0][aK + 0][aRow] = aReg.x;
    sA[0][aK + 1][aRow] = aReg.y;
    sA[0][aK + 2][aRow] = aReg.z;
    sA[0][aK + 3][aRow] = aReg.w;
    *(float4*)&sB[0][bK][bCol]     = bReg0;
    *(float4*)&sB[0][bK][bCol + 4] = bReg1;
    __syncthreads();

    for (int kt = 0; kt < KT; kt++) {
        const int k0n = (kt + 1) * 16;
        if (kt + 1 < KT) {
            aReg = make_float4(0.f, 0.f, 0.f, 0.f);
            const int ak = k0n + aK;
            if (m0 + aRow < S_DIM && ak < S_DIM)
                aReg = *(const float4*)(A + (m0 + aRow) * S_DIM + ak);
            bReg0 = make_float4(0.f, 0.f, 0.f, 0.f);
            bReg1 = bReg0;
            const int bk = k0n + bK;
            if (bk < S_DIM) {
                const float* bp = X + bk * CN + n0 + bCol;
                bReg0 = *(const float4*)(bp);
                bReg1 = *(const float4*)(bp + 4);
            }
        }
        #pragma unroll
        for (int k = 0; k < 16; k++) {
            float a4[4];
            *(float4*)a4 = *(const float4*)&sA[buf][k][tm4];
            unsigned long long ad[4], bp2[4];
            #pragma unroll
            for (int i = 0; i < 4; i++) DUP2(ad[i], a4[i]);
            #pragma unroll
            for (int j = 0; j < 4; j++)
                bp2[j] = *(const unsigned long long*)&sB[buf][k][tn2 + j * 32];
            #pragma unroll
            for (int i = 0; i < 4; i++)
                #pragma unroll
                for (int j = 0; j < 4; j++)
                    FMA2(acc[i][j], ad[i], bp2[j], acc[i][j]);
        }
        if (kt + 1 < KT) {
            __syncthreads();
            buf ^= 1;
            sA[buf][aK + 0][aRow] = aReg.x;
            sA[buf][aK + 1][aRow] = aReg.y;
            sA[buf][aK + 2][aRow] = aReg.z;
            sA[buf][aK + 3][aRow] = aReg.w;
            *(float4*)&sB[buf][bK][bCol]     = bReg0;
            *(float4*)&sB[buf][bK][bCol + 4] = bReg1;
            __syncthreads();
        }
    }

    #pragma unroll
    for (int mi = 0; mi < 4; mi++) {
        const int row = m0 + tm4 + mi;
        if (row < S_DIM) {
            float* cp = C + row * CN + n0;
            #pragma unroll
            for (int j = 0; j < 4; j++) {
                float2 v = unpack2(acc[mi][j]);
                *(float2*)(cp + j * 32 + tn2) = v;
            }
        }
    }
}

// ---------------------------------------------------------------------------
// Temporal combine: from m0=Z, m1, m2 build
//   y1 = Adj z   = s0 n00 + s1 n01 + s2 n10 + s3 n11
//   y2 = Adj^2 z = sum_{p,q<=2} c_pq n_pq   (n_pq = At^p (along t) of m_q)
// grid: 4000 CTAs = (b,s); 64 threads = f
// ---------------------------------------------------------------------------
__global__ __launch_bounds__(64)
void k_comb(const float* __restrict__ At, const float* __restrict__ sv)
{
    __shared__ float sAt[64];
    const int tid = threadIdx.x;
    const int bx  = blockIdx.x;         // b*500 + s
    const int b   = bx / 500;
    const int s   = bx - b * 500;
    sAt[tid] = At[tid];
    __syncthreads();

    const int base = s * CN + b * (T_DIM * FO) + tid;

    float m0[8], m1v[8], m2v[8];
    #pragma unroll
    for (int t = 0; t < 8; t++) {
        m0[t]  = g_Z [base + t * 64];
        m1v[t] = g_M1[base + t * 64];
        m2v[t] = g_M2[base + t * 64];
    }
    const float s0 = sv[0], s1 = sv[1], s2 = sv[2], s3 = sv[3];
    const float c00 = s0 * s0, c01 = 2.f * s0 * s1, c02 = s1 * s1;
    const float c10 = 2.f * s0 * s2, c11 = 2.f * (s0 * s3 + s1 * s2), c12 = 2.f * s1 * s3;
    const float c20 = s2 * s2, c21 = 2.f * s2 * s3, c22 = s3 * s3;

    float n10[8], n11[8], n12[8];
    #pragma unroll
    for (int t = 0; t < 8; t++) {
        float a0 = 0.f, a1 = 0.f, a2 = 0.f;
        #pragma unroll
        for (int u = 0; u < 8; u++) {
            const float w = sAt[t * 8 + u];
            a0 += w * m0[u]; a1 += w * m1v[u]; a2 += w * m2v[u];
        }
        n10[t] = a0; n11[t] = a1; n12[t] = a2;
    }
    #pragma unroll
    for (int t = 0; t < 8; t++) {
        float a0 = 0.f, a1 = 0.f, a2 = 0.f;
        #pragma unroll
        for (int u = 0; u < 8; u++) {
            const float w = sAt[t * 8 + u];
            a0 += w * n10[u]; a1 += w * n11[u]; a2 += w * n12[u];
        }
        const float y1 = s0 * m0[t] + s1 * m1v[t] + s2 * n10[t] + s3 * n11[t];
        const float y2 = c00 * m0[t] + c01 * m1v[t] + c02 * m2v[t]
                       + c10 * n10[t] + c11 * n11[t] + c12 * n12[t]
                       + c20 * a0 + c21 * a1 + c22 * a2;
        g_Y1[base + t * 64] = y1;
        g_Y2[base + t * 64] = y2;
    }
}

// ---------------------------------------------------------------------------
// Layer mix GEMM: Z[32000,64] = tanh( Z@H0 + Y1@H1 + Y2@H2 )   (in-place on Z)
// BM=128, BN=64(all), K=192 in 3 segs of 64; 256 threads; tile 8x4
// grid: 250 CTAs
// ---------------------------------------------------------------------------
__global__ __launch_bounds__(256)
void k_gemm2(const float* __restrict__ Hl)
{
    __shared__ __align__(16) float sH[64][68];
    __shared__ __align__(16) float sA[2][16][132];

    const int tid = threadIdx.x;
    const int r0  = blockIdx.x * 128;
    const int tc4 = (tid & 15) * 4;   // 4 consecutive output cols
    const int tm8 = (tid >> 4) * 8;   // 8 rows (4 row pairs)

    const int ar  = tid >> 1;         // 0..127
    const int akq = (tid & 1) * 8;    // 0 or 8

    unsigned long long acc[4][4];     // [row pair u][col j]
    #pragma unroll
    for (int i = 0; i < 4; i++)
        #pragma unroll
        for (int j = 0; j < 4; j++) acc[i][j] = 0ULL;

    const float* Ybufs[3] = { g_Z, g_Y1, g_Y2 };

    for (int seg = 0; seg < 3; seg++) {
        __syncthreads();   // protect sH/sA reuse from previous seg
        const float* Hs = Hl + seg * 4096;
        for (int idx = tid; idx < 4096; idx += 256)
            sH[idx >> 6][idx & 63] = Hs[idx];
        const float* Y = Ybufs[seg];

        float4 a0 = *(const float4*)(Y + (r0 + ar) * 64 + akq);
        float4 a1 = *(const float4*)(Y + (r0 + ar) * 64 + akq + 4);
        int buf = 0;
        {
            float av[8]; *(float4*)av = a0; *(float4*)(av + 4) = a1;
            #pragma unroll
            for (int j = 0; j < 8; j++) sA[0][akq + j][ar] = av[j];
        }
        __syncthreads();

        for (int ch = 0; ch < 4; ch++) {
            if (ch < 3) {
                const int kb = (ch + 1) * 16;
                a0 = *(const float4*)(Y + (r0 + ar) * 64 + kb + akq);
                a1 = *(const float4*)(Y + (r0 + ar) * 64 + kb + akq + 4);
            }
            #pragma unroll
            for (int k = 0; k < 16; k++) {
                const int kf = ch * 16 + k;
                float b4[4];
                *(float4*)b4 = *(const float4*)&sH[kf][tc4];
                unsigned long long bd[4], ap[4];
                #pragma unroll
                for (int j = 0; j < 4; j++) DUP2(bd[j], b4[j]);
                #pragma unroll
                for (int u = 0; u < 4; u++)
                    ap[u] = *(const unsigned long long*)&sA[buf][k][tm8 + 2 * u];
                #pragma unroll
                for (int u = 0; u < 4; u++)
                    #pragma unroll
                    for (int j = 0; j < 4; j++)
                        FMA2(acc[u][j], ap[u], bd[j], acc[u][j]);
            }
            if (ch < 3) {
                __syncthreads();
                buf ^= 1;
                float av[8]; *(float4*)av = a0; *(float4*)(av + 4) = a1;
                #pragma unroll
                for (int j = 0; j < 8; j++) sA[buf][akq + j][ar] = av[j];
                __syncthreads();
            }
        }
    }

    #pragma unroll
    for (int u = 0; u < 4; u++) {
        float2 v0 = unpack2(acc[u][0]);
        float2 v1 = unpack2(acc[u][1]);
        float2 v2 = unpack2(acc[u][2]);
        float2 v3 = unpack2(acc[u][3]);
        const int rlo = r0 + tm8 + 2 * u;
        float4 lo = make_float4(tanhf(v0.x), tanhf(v1.x), tanhf(v2.x), tanhf(v3.x));
        float4 hi = make_float4(tanhf(v0.y), tanhf(v1.y), tanhf(v2.y), tanhf(v3.y));
        *(float4*)(g_Z + rlo * 64 + tc4)       = lo;
        *(float4*)(g_Z + (rlo + 1) * 64 + tc4) = hi;
    }
}

// ---------------------------------------------------------------------------
// Output: out[b,s,g] = sum_f W2[g,f] * (sum_t merge[t] Z[s,(b,t,f)]) + (sum_t merge[t]) b2[g]
// grid: 4000 CTAs = (b,s); 64 threads = g
// ---------------------------------------------------------------------------
__global__ __launch_bounds__(64)
void k_out(const float* __restrict__ W2, const float* __restrict__ b2,
           const float* __restrict__ merge, float* __restrict__ out)
{
    __shared__ float su[64];
    __shared__ float sm[8];
    const int tid = threadIdx.x;
    const int bx  = blockIdx.x;       // b*500 + s
    const int b   = bx / 500;
    const int s   = bx - b * 500;
    if (tid < 8) sm[tid] = merge[tid];
    __syncthreads();

    const int base = s * CN + b * (T_DIM * FO) + tid;
    float acc = 0.f, msum = 0.f;
    #pragma unroll
    for (int t = 0; t < 8; t++) {
        acc  += sm[t] * g_Z[base + t * 64];
        msum += sm[t];
    }
    su[tid] = acc;
    __syncthreads();

    float o = msum * b2[tid];
    const float* w = W2 + tid * 64;
    #pragma unroll 8
    for (int f = 0; f < 64; f++) o += w[f] * su[f];
    out[bx * 64 + tid] = o;
}

// ---------------------------------------------------------------------------
extern "C" void kernel_launch(void* const* d_in, const int* in_sizes, int n_in,
                              void* d_out, int out_size)
{
    const float* x     = (const float*)d_in[0];
    const float* At    = (const float*)d_in[1];
    const float* As    = (const float*)d_in[2];
    const float* sv    = (const float*)d_in[3];
    const float* H     = (const float*)d_in[4];
    const float* W1    = (const float*)d_in[5];
    const float* b1    = (const float*)d_in[6];
    const float* W2    = (const float*)d_in[7];
    const float* b2    = (const float*)d_in[8];
    const float* merge = (const float*)d_in[9];
    float* out = (float*)d_out;

    float *Zp = nullptr, *M1p = nullptr, *M2p = nullptr;
    cudaGetSymbolAddress((void**)&Zp,  g_Z);
    cudaGetSymbolAddress((void**)&M1p, g_M1);
    cudaGetSymbolAddress((void**)&M2p, g_M2);

    k_inproj<<<dim3(64, 10), 256>>>(x, W1, b1);

    for (int l = 0; l < 3; l++) {
        k_gemm<<<dim3(32, 8), 256>>>(As, Zp,  M1p);   // m1 = As @ Z
        k_gemm<<<dim3(32, 8), 256>>>(As, M1p, M2p);   // m2 = As @ m1
        k_comb<<<4000, 64>>>(At, sv);                 // Y1, Y2
        k_gemm2<<<250, 256>>>(H + l * 3 * 64 * 64);   // Z = tanh(Z H0 + Y1 H1 + Y2 H2)
    }

    k_out<<<4000, 64>>>(W2, b2, merge, out);
}

// round 3
// speedup vs baseline: 1.3535x; 1.3535x over previous
#include <cuda_runtime.h>
#include <cuda_bf16.h>
#include <cstdint>
#include <math.h>

// Problem constants
#define S_DIM 500
#define T_DIM 8
#define FO    64
#define CN    4096          // B*T*FO
#define KP    512           // padded spatial dim
#define KBIG  1536          // 3 * KP  (split-concat K for main GEMM)
#define K2    576           // 3 * 192 (split-concat K for mix GEMM)
#define M2R   32000         // S * 64 rows of mix GEMM

// ---------------- device scratch (allocation-free) ----------------
__device__ float          g_Z   [S_DIM * CN];     // fp32 activations [s][n]
__device__ float          g_C   [1024 * CN];      // rows 0..499: As@Z ; rows 512..1011: As^2@Z
__device__ float          g_As2 [KP * KP];
__device__ __nv_bfloat16  g_Abig[1024 * KBIG];    // [As; As2] K-concat [hi|hi|lo]
__device__ __nv_bfloat16  g_BT  [KP * KBIG];      // As^T K-concat [hi|lo|hi]
__device__ __nv_bfloat16  g_Bbig[CN * KBIG];      // Z^T  K-concat [hi|lo|hi]
__device__ __nv_bfloat16  g_A2  [(size_t)M2R * K2]; // [Z|Y1|Y2] splits, A side [hi|hi|lo] per seg
__device__ __nv_bfloat16  g_Ht  [3 * FO * K2];    // per-layer H^T splits, B side [hi|lo|hi] per seg

// ---------------- helpers ----------------
static __device__ __forceinline__ uint32_t smem_u32(const void* p) {
    uint32_t a;
    asm("{ .reg .u64 t; cvta.to.shared.u64 t, %1; cvt.u32.u64 %0, t; }" : "=r"(a) : "l"(p));
    return a;
}
static __device__ __forceinline__ void split_bf16(float v, __nv_bfloat16& h, __nv_bfloat16& l) {
    h = __float2bfloat16(v);
    l = __float2bfloat16(v - __bfloat162float(h));
}

#define CP_ASYNC16(s, g) asm volatile("cp.async.cg.shared.global [%0], [%1], 16;" :: "r"(s), "l"(g))
#define CP_COMMIT()      asm volatile("cp.async.commit_group;")
#define CP_WAIT0()       asm volatile("cp.async.wait_group 0;")
#define CP_WAIT1()       asm volatile("cp.async.wait_group 1;")

#define LDSM4(r0, r1, r2, r3, a)                                                     \
    asm volatile("ldmatrix.sync.aligned.m8n8.x4.shared.b16 {%0,%1,%2,%3}, [%4];"     \
        : "=r"(r0), "=r"(r1), "=r"(r2), "=r"(r3) : "r"(a))

#define MMA16816(d, a0, a1, a2, a3, b0, b1)                                          \
    asm volatile("mma.sync.aligned.m16n8k16.row.col.f32.bf16.bf16.f32 "              \
        "{%0,%1,%2,%3}, {%4,%5,%6,%7}, {%8,%9}, {%0,%1,%2,%3};"                      \
        : "+f"((d)[0]), "+f"((d)[1]), "+f"((d)[2]), "+f"((d)[3])                     \
        : "r"(a0), "r"(a1), "r"(a2), "r"(a3), "r"(b0), "r"(b1))

// Row stride in smem: 64 bf16 + 8 pad = 72 elems = 144 B (16B-aligned, ldmatrix
// conflict-free: 8 rows land on banks {0,4,..,28}*4B distinct).
#define SROW 144
#define ATILE_B (128 * SROW)        // 18432 bytes per 128x64 bf16 tile

// ---------------------------------------------------------------------------
// tg_main: C[128 x 128 tile] = A[m0:,K] @ B[n0:,K]^T, bf16 K-contig, fp32 out
// BM=128 BN=128 BK=64, 256 thr, warps 2(M)x4(N), warp tile 64x32.
// ---------------------------------------------------------------------------
__global__ __launch_bounds__(256)
void tg_main(const __nv_bfloat16* __restrict__ A, const __nv_bfloat16* __restrict__ B,
             float* __restrict__ C, int K, int ldc)
{
    extern __shared__ char smem[];
    const uint32_t sb = smem_u32(smem);
    const int BUFSZ = 2 * ATILE_B;              // A + B per buffer = 36864

    const int tid  = threadIdx.x;
    const int lane = tid & 31, w = tid >> 5;
    const int wm = w >> 2, wn = w & 3;          // 2 x 4 warps
    const int m0 = blockIdx.y * 128;
    const int n0 = blockIdx.x * 128;
    const int NIT = K >> 6;

    // loader mapping: 4 x 16B chunks for A, 4 for B
    const int lrow = (tid * 4) >> 3 >> 2;  // dummy avoid warn
    (void)lrow;

    // ldmatrix offsets (within a buffer)
    uint32_t aOff[4], bOff[2];
    {
        const int acb = (lane >> 4) * 16;
        #pragma unroll
        for (int i = 0; i < 4; i++) {
            const int r = wm * 64 + i * 16 + ((lane >> 3) & 1) * 8 + (lane & 7);
            aOff[i] = (uint32_t)(r * SROW + acb);
        }
        const int bcb = ((lane >> 3) & 1) * 16;
        #pragma unroll
        for (int p = 0; p < 2; p++) {
            const int r = wn * 32 + p * 16 + (lane >> 4) * 8 + (lane & 7);
            bOff[p] = (uint32_t)(ATILE_B + r * SROW + bcb);
        }
    }

    float acc[4][4][4];
    #pragma unroll
    for (int i = 0; i < 4; i++)
        #pragma unroll
        for (int j = 0; j < 4; j++)
            #pragma unroll
            for (int q = 0; q < 4; q++) acc[i][j][q] = 0.f;

    // global load helper (as macro-ish lambda)
    auto load_tiles = [&](int it, int buf) {
        const uint32_t dst = sb + buf * BUFSZ;
        const __nv_bfloat16* ga = A + (size_t)m0 * K + it * 64;
        const __nv_bfloat16* gb = B + (size_t)n0 * K + it * 64;
        #pragma unroll
        for (int i = 0; i < 4; i++) {
            const int ch = i * 256 + tid;       // 0..1023
            const int r = ch >> 3, c = ch & 7;
            CP_ASYNC16(dst + r * SROW + c * 16, ga + (size_t)r * K + c * 8);
        }
        #pragma unroll
        for (int i = 0; i < 4; i++) {
            const int ch = i * 256 + tid;
            const int r = ch >> 3, c = ch & 7;
            CP_ASYNC16(dst + ATILE_B + r * SROW + c * 16, gb + (size_t)r * K + c * 8);
        }
    };

    load_tiles(0, 0);
    CP_COMMIT();

    int buf = 0;
    for (int it = 0; it < NIT; it++) {
        if (it + 1 < NIT) { load_tiles(it + 1, buf ^ 1); CP_COMMIT(); CP_WAIT1(); }
        else             { CP_WAIT0(); }
        __syncthreads();

        const uint32_t base = sb + buf * BUFSZ;
        #pragma unroll
        for (int ks = 0; ks < 4; ks++) {
            uint32_t am[4][4], bm[2][4];
            #pragma unroll
            for (int i = 0; i < 4; i++)
                LDSM4(am[i][0], am[i][1], am[i][2], am[i][3], base + aOff[i] + ks * 32);
            #pragma unroll
            for (int p = 0; p < 2; p++)
                LDSM4(bm[p][0], bm[p][1], bm[p][2], bm[p][3], base + bOff[p] + ks * 32);
            #pragma unroll
            for (int i = 0; i < 4; i++) {
                #pragma unroll
                for (int j = 0; j < 4; j++) {
                    const uint32_t b0 = bm[j >> 1][(j & 1) * 2];
                    const uint32_t b1 = bm[j >> 1][(j & 1) * 2 + 1];
                    MMA16816(acc[i][j], am[i][0], am[i][1], am[i][2], am[i][3], b0, b1);
                }
            }
        }
        __syncthreads();
        buf ^= 1;
    }

    // epilogue
    #pragma unroll
    for (int i = 0; i < 4; i++) {
        const int row = m0 + wm * 64 + i * 16 + (lane >> 2);
        #pragma unroll
        for (int j = 0; j < 4; j++) {
            const int col = n0 + wn * 32 + j * 8 + (lane & 3) * 2;
            *(float2*)&C[(size_t)row * ldc + col]       = make_float2(acc[i][j][0], acc[i][j][1]);
            *(float2*)&C[(size_t)(row + 8) * ldc + col] = make_float2(acc[i][j][2], acc[i][j][3]);
        }
    }
}

// ---------------------------------------------------------------------------
// tg_mix: Z <- tanh( A2[32000,576] @ Ht[64,576]^T ), scatter back into g_Z
// BM=128 BN=64 BK=64, 256 thr, warps 4(M)x2(N), warp tile 32x32. grid 250.
// ---------------------------------------------------------------------------
#define BTILE2_B (64 * SROW)        // 9216
__global__ __launch_bounds__(256)
void tg_mix(const __nv_bfloat16* __restrict__ A, const __nv_bfloat16* __restrict__ B)
{
    extern __shared__ char smem[];
    const uint32_t sb = smem_u32(smem);
    const int BUFSZ = ATILE_B + BTILE2_B;   // 27648

    const int tid  = threadIdx.x;
    const int lane = tid & 31, w = tid >> 5;
    const int wm = w >> 1, wn = w & 1;      // 4 x 2 warps
    const int r0 = blockIdx.x * 128;
    const int K = K2;
    const int NIT = K / 64;                 // 9

    uint32_t aOff[2], bOff[2];
    {
        const int acb = (lane >> 4) * 16;
        #pragma unroll
        for (int i = 0; i < 2; i++) {
            const int r = wm * 32 + i * 16 + ((lane >> 3) & 1) * 8 + (lane & 7);
            aOff[i] = (uint32_t)(r * SROW + acb);
        }
        const int bcb = ((lane >> 3) & 1) * 16;
        #pragma unroll
        for (int p = 0; p < 2; p++) {
            const int r = wn * 32 + p * 16 + (lane >> 4) * 8 + (lane & 7);
            bOff[p] = (uint32_t)(ATILE_B + r * SROW + bcb);
        }
    }

    float acc[2][4][4];
    #pragma unroll
    for (int i = 0; i < 2; i++)
        #pragma unroll
        for (int j = 0; j < 4; j++)
            #pragma unroll
            for (int q = 0; q < 4; q++) acc[i][j][q] = 0.f;

    auto load_tiles = [&](int it, int bufi) {
        const uint32_t dst = sb + bufi * BUFSZ;
        const __nv_bfloat16* ga = A + (size_t)r0 * K + it * 64;
        const __nv_bfloat16* gb = B + it * 64;
        #pragma unroll
        for (int i = 0; i < 4; i++) {
            const int ch = i * 256 + tid;
            const int r = ch >> 3, c = ch & 7;
            CP_ASYNC16(dst + r * SROW + c * 16, ga + (size_t)r * K + c * 8);
        }
        #pragma unroll
        for (int i = 0; i < 2; i++) {
            const int ch = i * 256 + tid;   // 0..511
            const int r = ch >> 3, c = ch & 7;
            CP_ASYNC16(dst + ATILE_B + r * SROW + c * 16, gb + (size_t)r * K + c * 8);
        }
    };

    load_tiles(0, 0);
    CP_COMMIT();

    int buf = 0;
    for (int it = 0; it < NIT; it++) {
        if (it + 1 < NIT) { load_tiles(it + 1, buf ^ 1); CP_COMMIT(); CP_WAIT1(); }
        else             { CP_WAIT0(); }
        __syncthreads();

        const uint32_t base = sb + buf * BUFSZ;
        #pragma unroll
        for (int ks = 0; ks < 4; ks++) {
            uint32_t am[2][4], bm[2][4];
            #pragma unroll
            for (int i = 0; i < 2; i++)
                LDSM4(am[i][0], am[i][1], am[i][2], am[i][3], base + aOff[i] + ks * 32);
            #pragma unroll
            for (int p = 0; p < 2; p++)
                LDSM4(bm[p][0], bm[p][1], bm[p][2], bm[p][3], base + bOff[p] + ks * 32);
            #pragma unroll
            for (int i = 0; i < 2; i++) {
                #pragma unroll
                for (int j = 0; j < 4; j++) {
                    const uint32_t b0 = bm[j >> 1][(j & 1) * 2];
                    const uint32_t b1 = bm[j >> 1][(j & 1) * 2 + 1];
                    MMA16816(acc[i][j], am[i][0], am[i][1], am[i][2], am[i][3], b0, b1);
                }
            }
        }
        __syncthreads();
        buf ^= 1;
    }

    // epilogue: tanh + scatter into g_Z[s][bt*64 + col]
    #pragma unroll
    for (int i = 0; i < 2; i++) {
        #pragma unroll
        for (int h = 0; h < 2; h++) {
            const int rr = r0 + wm * 32 + i * 16 + (lane >> 2) + h * 8;
            const int s = rr >> 6, bt = rr & 63;
            float* zp = g_Z + (size_t)s * CN + bt * 64;
            #pragma unroll
            for (int j = 0; j < 4; j++) {
                const int col = wn * 32 + j * 8 + (lane & 3) * 2;
                zp[col]     = tanhf(acc[i][j][h * 2 + 0]);
                zp[col + 1] = tanhf(acc[i][j][h * 2 + 1]);
            }
        }
    }
}

// ---------------------------------------------------------------------------
// k_split_as: As -> Abig rows 0..511 ([hi|hi|lo]) + BT (As^T, [hi|lo|hi])
// ---------------------------------------------------------------------------
__global__ __launch_bounds__(256)
void k_split_as(const float* __restrict__ As)
{
    __shared__ float tile[32][33];
    const int tid = threadIdx.x;
    const int tr = tid >> 5, tc = tid & 31;
    const int r0 = blockIdx.y * 32, c0 = blockIdx.x * 32;

    #pragma unroll
    for (int ii = 0; ii < 4; ii++) {
        const int r = r0 + tr + ii * 8, c = c0 + tc;
        float v = (r < S_DIM && c < S_DIM) ? As[r * S_DIM + c] : 0.f;
        __nv_bfloat16 h, l; split_bf16(v, h, l);
        __nv_bfloat16* ap = g_Abig + (size_t)r * KBIG;
        ap[c] = h; ap[KP + c] = h; ap[2 * KP + c] = l;
        tile[tr + ii * 8][tc] = v;
    }
    __syncthreads();
    #pragma unroll
    for (int ii = 0; ii < 4; ii++) {
        const int a = tr + ii * 8;
        const float v = tile[tc][a];
        __nv_bfloat16 h, l; split_bf16(v, h, l);
        __nv_bfloat16* bp = g_BT + (size_t)(c0 + a) * KBIG;
        bp[r0 + tc] = h; bp[KP + r0 + tc] = l; bp[2 * KP + r0 + tc] = h;
    }
}

// ---------------------------------------------------------------------------
// k_split_a2: g_As2 fp32 -> Abig rows 512..1023 ([hi|hi|lo])
// ---------------------------------------------------------------------------
__global__ __launch_bounds__(256)
void k_split_a2()
{
    const int base = (blockIdx.x * 256 + threadIdx.x) * 4;
    #pragma unroll
    for (int i = 0; i < 4; i++) {
        const int idx = base + i;             // < 512*512
        const int r = idx >> 9, k = idx & 511;
        __nv_bfloat16 h, l; split_bf16(g_As2[idx], h, l);
        __nv_bfloat16* ap = g_Abig + (size_t)(KP + r) * KBIG;
        ap[k] = h; ap[KP + k] = h; ap[2 * KP + k] = l;
    }
}

// ---------------------------------------------------------------------------
// k_splitT_z: Z[500,4096] -> Bbig[4096][1536] (transpose + split [hi|lo|hi])
// ---------------------------------------------------------------------------
__global__ __launch_bounds__(256)
void k_splitT_z()
{
    __shared__ float tile[32][33];
    const int tid = threadIdx.x;
    const int tr = tid >> 5, tc = tid & 31;
    const int r0 = blockIdx.y * 32;   // s
    const int c0 = blockIdx.x * 32;   // n

    #pragma unroll
    for (int ii = 0; ii < 4; ii++) {
        const int r = r0 + tr + ii * 8;
        tile[tr + ii * 8][tc] = (r < S_DIM) ? g_Z[(size_t)r * CN + c0 + tc] : 0.f;
    }
    __syncthreads();
    #pragma unroll
    for (int ii = 0; ii < 4; ii++) {
        const int a = tr + ii * 8;
        const float v = tile[tc][a];
        __nv_bfloat16 h, l; split_bf16(v, h, l);
        __nv_bfloat16* bp = g_Bbig + (size_t)(c0 + a) * KBIG;
        bp[r0 + tc] = h; bp[KP + r0 + tc] = l; bp[2 * KP + r0 + tc] = h;
    }
}

// ---------------------------------------------------------------------------
// k_ht: per-layer H -> Ht[64][576]  B-side splits ([hi|lo|hi] per seg)
// grid 3 (layers)
// ---------------------------------------------------------------------------
__global__ __launch_bounds__(256)
void k_ht(const float* __restrict__ H)
{
    const int l = blockIdx.x;
    for (int idx = threadIdx.x; idx < 3 * 64 * 64; idx += 256) {
        const int seg = idx >> 12, rem = idx & 4095;
        const int f = rem >> 6, g = rem & 63;
        const float v = H[l * 12288 + seg * 4096 + f * 64 + g];
        __nv_bfloat16 h, lo; split_bf16(v, h, lo);
        __nv_bfloat16* hp = g_Ht + (size_t)l * FO * K2 + (size_t)g * K2 + seg * 192;
        hp[f] = h; hp[64 + f] = lo; hp[128 + f] = h;
    }
}

// ---------------------------------------------------------------------------
// k_inproj
// ---------------------------------------------------------------------------
__global__ __launch_bounds__(256)
void k_inproj(const float* __restrict__ x, const float* __restrict__ W1,
              const float* __restrict__ b1)
{
    __shared__ float ws[FO][33];
    __shared__ float xs[50][32];
    __shared__ float bs[FO];

    const int tid = threadIdx.x;
    const int bt  = blockIdx.x;
    const int s0  = blockIdx.y * 50;

    for (int idx = tid; idx < FO * 32; idx += 256)
        ws[idx >> 5][idx & 31] = W1[idx];
    if (tid < FO) bs[tid] = b1[tid];
    const float* xp = x + (bt * S_DIM + s0) * 32;
    for (int idx = tid; idx < 50 * 32; idx += 256)
        xs[idx >> 5][idx & 31] = xp[idx];
    __syncthreads();

    const int f   = tid & 63;
    const int sl0 = tid >> 6;
    for (int sl = sl0; sl < 50; sl += 4) {
        float acc = bs[f];
        #pragma unroll
        for (int i = 0; i < 32; i++)
            acc += xs[sl][i] * ws[f][i];
        g_Z[(size_t)(s0 + sl) * CN + bt * FO + f] = acc;
    }
}

// ---------------------------------------------------------------------------
// k_comb: temporal mixing; writes A-operand g_A2 ([hi|hi|lo] per seg) directly
// grid 1000 x 256 thr (4 (b,s) groups per CTA)
// ---------------------------------------------------------------------------
__global__ __launch_bounds__(256)
void k_comb(const float* __restrict__ At, const float* __restrict__ sv)
{
    __shared__ float sAt[64];
    const int tid = threadIdx.x;
    if (tid < 64) sAt[tid] = At[tid];
    __syncthreads();

    const int g  = tid >> 6, f = tid & 63;
    const int bx = blockIdx.x * 4 + g;      // 0..3999
    const int b  = bx / 500;
    const int s  = bx - b * 500;

    const size_t base = (size_t)s * CN + b * (T_DIM * FO) + f;
    const size_t m2off = (size_t)KP * CN;

    float m0[8], m1v[8], m2v[8];
    #pragma unroll
    for (int t = 0; t < 8; t++) {
        m0[t]  = g_Z[base + t * 64];
        m1v[t] = g_C[base + t * 64];
        m2v[t] = g_C[m2off + base + t * 64];
    }
    const float s0 = sv[0], s1 = sv[1], s2 = sv[2], s3 = sv[3];
    const float c00 = s0 * s0, c01 = 2.f * s0 * s1, c02 = s1 * s1;
    const float c10 = 2.f * s0 * s2, c11 = 2.f * (s0 * s3 + s1 * s2), c12 = 2.f * s1 * s3;
    const float c20 = s2 * s2, c21 = 2.f * s2 * s3, c22 = s3 * s3;

    float n10[8], n11[8], n12[8];
    #pragma unroll
    for (int t = 0; t < 8; t++) {
        float a0 = 0.f, a1 = 0.f, a2 = 0.f;
        #pragma unroll
        for (int u = 0; u < 8; u++) {
            const float w = sAt[t * 8 + u];
            a0 += w * m0[u]; a1 += w * m1v[u]; a2 += w * m2v[u];
        }
        n10[t] = a0; n11[t] = a1; n12[t] = a2;
    }
    #pragma unroll
    for (int t = 0; t < 8; t++) {
        float a0 = 0.f, a1 = 0.f, a2 = 0.f;
        #pragma unroll
        for (int u = 0; u < 8; u++) {
            const float w = sAt[t * 8 + u];
            a0 += w * n10[u]; a1 += w * n11[u]; a2 += w * n12[u];
        }
        const float y1 = s0 * m0[t] + s1 * m1v[t] + s2 * n10[t] + s3 * n11[t];
        const float y2 = c00 * m0[t] + c01 * m1v[t] + c02 * m2v[t]
                       + c10 * n10[t] + c11 * n11[t] + c12 * n12[t]
                       + c20 * a0 + c21 * a1 + c22 * a2;

        __nv_bfloat16* ap = g_A2 + (size_t)(s * 64 + b * 8 + t) * K2;
        __nv_bfloat16 h, lo;
        split_bf16(m0[t], h, lo);
        ap[f] = h; ap[64 + f] = h; ap[128 + f] = lo;
        split_bf16(y1, h, lo);
        ap[192 + f] = h; ap[256 + f] = h; ap[320 + f] = lo;
        split_bf16(y2, h, lo);
        ap[384 + f] = h; ap[448 + f] = h; ap[512 + f] = lo;
    }
}

// ---------------------------------------------------------------------------
// k_out
// ---------------------------------------------------------------------------
__global__ __launch_bounds__(64)
void k_out(const float* __restrict__ W2, const float* __restrict__ b2,
           const float* __restrict__ merge, float* __restrict__ out)
{
    __shared__ float su[64];
    __shared__ float sm[8];
    const int tid = threadIdx.x;
    const int bx  = blockIdx.x;
    const int b   = bx / 500;
    const int s   = bx - b * 500;
    if (tid < 8) sm[tid] = merge[tid];
    __syncthreads();

    const size_t base = (size_t)s * CN + b * (T_DIM * FO) + tid;
    float acc = 0.f, msum = 0.f;
    #pragma unroll
    for (int t = 0; t < 8; t++) {
        acc  += sm[t] * g_Z[base + t * 64];
        msum += sm[t];
    }
    su[tid] = acc;
    __syncthreads();

    float o = msum * b2[tid];
    const float* w = W2 + tid * 64;
    #pragma unroll 8
    for (int f = 0; f < 64; f++) o += w[f] * su[f];
    out[bx * 64 + tid] = o;
}

// ---------------------------------------------------------------------------
extern "C" void kernel_launch(void* const* d_in, const int* in_sizes, int n_in,
                              void* d_out, int out_size)
{
    const float* x     = (const float*)d_in[0];
    const float* At    = (const float*)d_in[1];
    const float* As    = (const float*)d_in[2];
    const float* sv    = (const float*)d_in[3];
    const float* H     = (const float*)d_in[4];
    const float* W1    = (const float*)d_in[5];
    const float* b1    = (const float*)d_in[6];
    const float* W2    = (const float*)d_in[7];
    const float* b2    = (const float*)d_in[8];
    const float* merge = (const float*)d_in[9];
    float* out = (float*)d_out;

    const int SM_MAIN = 2 * (2 * ATILE_B);             // 73728
    const int SM_MIX  = 2 * (ATILE_B + BTILE2_B);      // 55296
    cudaFuncSetAttribute(tg_main, cudaFuncAttributeMaxDynamicSharedMemorySize, SM_MAIN);
    cudaFuncSetAttribute(tg_mix,  cudaFuncAttributeMaxDynamicSharedMemorySize, SM_MIX);

    __nv_bfloat16 *Abig, *BT, *Bbig, *A2, *Ht;
    float *As2p, *Cp;
    cudaGetSymbolAddress((void**)&Abig, g_Abig);
    cudaGetSymbolAddress((void**)&BT,   g_BT);
    cudaGetSymbolAddress((void**)&Bbig, g_Bbig);
    cudaGetSymbolAddress((void**)&A2,   g_A2);
    cudaGetSymbolAddress((void**)&Ht,   g_Ht);
    cudaGetSymbolAddress((void**)&As2p, g_As2);
    cudaGetSymbolAddress((void**)&Cp,   g_C);

    k_ht<<<3, 256>>>(H);
    k_split_as<<<dim3(16, 16), 256>>>(As);
    // As2 = As @ As  (M=512, N=512, K=1536)
    tg_main<<<dim3(4, 4), 256, SM_MAIN>>>(Abig, BT, As2p, KBIG, KP);
    k_split_a2<<<256, 256>>>();

    k_inproj<<<dim3(64, 10), 256>>>(x, W1, b1);

    for (int l = 0; l < 3; l++) {
        k_splitT_z<<<dim3(128, 16), 256>>>();
        // C[1024,4096] = [As;As2] @ Z^T   (K=1536)
        tg_main<<<dim3(32, 8), 256, SM_MAIN>>>(Abig, Bbig, Cp, KBIG, CN);
        k_comb<<<1000, 256>>>(At, sv);
        // Z = tanh(A2 @ Ht^T)
        tg_mix<<<250, 256, SM_MIX>>>(A2, Ht + (size_t)l * FO * K2);
    }

    k_out<<<4000, 64>>>(W2, b2, merge, out);
}